// round 2
// baseline (speedup 1.0000x reference)
#include <cuda_runtime.h>
#include <cuda_bf16.h>
#include <cstdint>

// ============================================================================
// out[4096,4096] = x[4096,4096] @ w_q^T, w_q = groupwise ternary(weight)
// bf16x3 emulation on HMMA (mma.sync, sm_100-safe; tcgen05 is 'a'-only).
// ============================================================================
#define M_DIM 4096
#define N_DIM 4096
#define K_DIM 4096
#define GROUP_SIZE 128

#define BM 128
#define BN 128
#define BK 32
#define KTILES (K_DIM / BK)        // 128
#define NSTAGE 3
#define NTHREADS 256

// smem: padded rows, 32 bf16 + 8 pad = 40 elems = 80 B  (stride 20 banks ->
// ldmatrix 8-row groups hit disjoint bank quads; conflict-free, no swizzle)
#define ROW_B 80
#define MAT_B (BM * ROW_B)         // 10240 bytes per 128x32 tile
#define STAGE_B (4 * MAT_B)        // Ah, Al, Bh, Bl
#define SMEM_B (NSTAGE * STAGE_B)  // 122880

// ============================================================================
// Device-global scratch (allocation-free rule)
// ============================================================================
__device__ __align__(1024) __nv_bfloat16 g_xh[(size_t)M_DIM * K_DIM];
__device__ __align__(1024) __nv_bfloat16 g_xl[(size_t)M_DIM * K_DIM];
__device__ __align__(1024) __nv_bfloat16 g_wh[(size_t)N_DIM * K_DIM];
__device__ __align__(1024) __nv_bfloat16 g_wl[(size_t)N_DIM * K_DIM];

// ============================================================================
// PTX helpers
// ============================================================================
__device__ __forceinline__ uint32_t smem_u32(const void* p) {
    uint32_t a;
    asm("{ .reg .u64 t; cvta.to.shared.u64 t, %1; cvt.u32.u64 %0, t; }"
        : "=r"(a) : "l"(p));
    return a;
}

#define CP_ASYNC_16(saddr, gaddr) \
    asm volatile("cp.async.cg.shared.global [%0], [%1], 16;" \
        :: "r"(saddr), "l"(gaddr))

#define CP_ASYNC_COMMIT() asm volatile("cp.async.commit_group;" ::: "memory")

#define CP_ASYNC_WAIT1() asm volatile("cp.async.wait_group 1;" ::: "memory")

#define LDSM_X4(r, addr) \
    asm volatile("ldmatrix.sync.aligned.m8n8.x4.shared.b16 {%0,%1,%2,%3}, [%4];" \
        : "=r"((r)[0]), "=r"((r)[1]), "=r"((r)[2]), "=r"((r)[3]) : "r"(addr))

#define MMA16816(d, a, b0, b1) \
    asm volatile("mma.sync.aligned.m16n8k16.row.col.f32.bf16.bf16.f32 " \
        "{%0,%1,%2,%3}, {%4,%5,%6,%7}, {%8,%9}, {%0,%1,%2,%3};" \
        : "+f"((d)[0]), "+f"((d)[1]), "+f"((d)[2]), "+f"((d)[3]) \
        : "r"((a)[0]), "r"((a)[1]), "r"((a)[2]), "r"((a)[3]), "r"(b0), "r"(b1))

// ============================================================================
// Preprocessing: split x into bf16 hi/lo
// ============================================================================
__global__ void split_x_kernel(const float* __restrict__ x, int n4) {
    int i = blockIdx.x * blockDim.x + threadIdx.x;
    int stride = gridDim.x * blockDim.x;
    for (; i < n4; i += stride) {
        float4 v = reinterpret_cast<const float4*>(x)[i];
        float vals[4] = {v.x, v.y, v.z, v.w};
        __nv_bfloat16 h[4], l[4];
#pragma unroll
        for (int j = 0; j < 4; j++) {
            h[j] = __float2bfloat16(vals[j]);
            l[j] = __float2bfloat16(vals[j] - __bfloat162float(h[j]));
        }
        size_t base = (size_t)i * 4;
        __nv_bfloat162 h01; h01.x = h[0]; h01.y = h[1];
        __nv_bfloat162 h23; h23.x = h[2]; h23.y = h[3];
        __nv_bfloat162 l01; l01.x = l[0]; l01.y = l[1];
        __nv_bfloat162 l23; l23.x = l[2]; l23.y = l[3];
        *reinterpret_cast<__nv_bfloat162*>(g_xh + base)     = h01;
        *reinterpret_cast<__nv_bfloat162*>(g_xh + base + 2) = h23;
        *reinterpret_cast<__nv_bfloat162*>(g_xl + base)     = l01;
        *reinterpret_cast<__nv_bfloat162*>(g_xl + base + 2) = l23;
    }
}

// Ternary-quantize weight groupwise + split into bf16 hi/lo. One warp/group.
__global__ void quant_split_w_kernel(const float* __restrict__ w) {
    int warp = blockIdx.x * (blockDim.x >> 5) + (threadIdx.x >> 5);
    int lane = threadIdx.x & 31;
    const float4 v = reinterpret_cast<const float4*>(w + (size_t)warp * GROUP_SIZE)[lane];
    float s = fabsf(v.x) + fabsf(v.y) + fabsf(v.z) + fabsf(v.w);
#pragma unroll
    for (int o = 16; o; o >>= 1) s += __shfl_xor_sync(0xffffffffu, s, o);
    float scale = fmaxf(s * (1.0f / GROUP_SIZE), 1e-8f);

    float vals[4] = {v.x, v.y, v.z, v.w};
    __nv_bfloat16 h[4], l[4];
#pragma unroll
    for (int j = 0; j < 4; j++) {
        float wn = vals[j] / scale;
        float q = (wn > 0.5f) ? 1.0f : ((wn < -0.5f) ? -1.0f : 0.0f);
        float wq = q * scale;
        h[j] = __float2bfloat16(wq);
        l[j] = __float2bfloat16(wq - __bfloat162float(h[j]));
    }
    size_t base = (size_t)warp * GROUP_SIZE + lane * 4;
    __nv_bfloat162 h01; h01.x = h[0]; h01.y = h[1];
    __nv_bfloat162 h23; h23.x = h[2]; h23.y = h[3];
    __nv_bfloat162 l01; l01.x = l[0]; l01.y = l[1];
    __nv_bfloat162 l23; l23.x = l[2]; l23.y = l[3];
    *reinterpret_cast<__nv_bfloat162*>(g_wh + base)     = h01;
    *reinterpret_cast<__nv_bfloat162*>(g_wh + base + 2) = h23;
    *reinterpret_cast<__nv_bfloat162*>(g_wl + base)     = l01;
    *reinterpret_cast<__nv_bfloat162*>(g_wl + base + 2) = l23;
}

// ============================================================================
// GEMM: acc += xh*wh + xl*wh + xh*wl  (fp32 accum in registers)
// 128x128 CTA tile, 8 warps @ 64x32, BK=32, 3-stage cp.async pipeline.
// ============================================================================
__device__ __forceinline__ void prefetch_stage(uint32_t sbase, int stage, int kt,
                                               int row0, int col0, int tid) {
    uint32_t st = sbase + stage * STAGE_B;
    const __nv_bfloat16* gsrc[4] = {
        g_xh, g_xl, g_wh, g_wl
    };
    int base_row[4] = { row0, row0, col0, col0 };
#pragma unroll
    for (int m = 0; m < 4; m++) {
#pragma unroll
        for (int i = 0; i < 2; i++) {
            int chunk = tid + i * NTHREADS;     // 0..511
            int row = chunk >> 2;               // 0..127
            int c16 = chunk & 3;                // 16B chunk within 64B row
            const __nv_bfloat16* g = gsrc[m] +
                (size_t)(base_row[m] + row) * K_DIM + kt * BK + c16 * 8;
            uint32_t sa = st + m * MAT_B + row * ROW_B + c16 * 16;
            CP_ASYNC_16(sa, g);
        }
    }
}

__global__ void __launch_bounds__(NTHREADS, 1) bitlinear_gemm_kernel(
    float* __restrict__ out)
{
    extern __shared__ __align__(128) unsigned char smem_raw[];
    const uint32_t sbase = smem_u32(smem_raw);
    const int tid = threadIdx.x;
    const int wid = tid >> 5;
    const int lane = tid & 31;
    const int wm = wid & 1;          // 2 warps along M (64 rows each)
    const int wn = wid >> 1;         // 4 warps along N (32 cols each)
    const int row0 = blockIdx.y * BM;
    const int col0 = blockIdx.x * BN;

    // per-thread ldmatrix address components (byte offsets within a tile)
    const uint32_t a_row = (wm * 64 + (lane & 15)) * ROW_B;
    const uint32_t a_col = (lane & 16) ? 16u : 0u;               // +8 elems
    const uint32_t b_row = (wn * 32 + (lane & 7) + ((lane & 16) >> 1)) * ROW_B;
    const uint32_t b_col = (lane & 8) ? 16u : 0u;

    float acc[4][4][4];
#pragma unroll
    for (int i = 0; i < 4; i++)
#pragma unroll
        for (int j = 0; j < 4; j++)
#pragma unroll
            for (int k = 0; k < 4; k++) acc[i][j][k] = 0.0f;

    // prologue: 2 stages in flight
    prefetch_stage(sbase, 0, 0, row0, col0, tid);
    CP_ASYNC_COMMIT();
    prefetch_stage(sbase, 1, 1, row0, col0, tid);
    CP_ASYNC_COMMIT();

    int stage = 0;
    for (int kt = 0; kt < KTILES; kt++) {
        CP_ASYNC_WAIT1();
        __syncthreads();

        if (kt + 2 < KTILES) {
            int ns = stage + 2; if (ns >= NSTAGE) ns -= NSTAGE;
            prefetch_stage(sbase, ns, kt + 2, row0, col0, tid);
        }
        CP_ASYNC_COMMIT();   // commit even if empty to keep group count regular

        const uint32_t st = sbase + stage * STAGE_B;
        const uint32_t s_ah = st + 0 * MAT_B;
        const uint32_t s_al = st + 1 * MAT_B;
        const uint32_t s_bh = st + 2 * MAT_B;
        const uint32_t s_bl = st + 3 * MAT_B;

#pragma unroll
        for (int k16 = 0; k16 < BK / 16; k16++) {
            const uint32_t kb = k16 * 32;   // 16 elems * 2B

            uint32_t ah[4][4], at[4][4], bq[2][4];
            // ---- load Ah, Bh
#pragma unroll
            for (int mi = 0; mi < 4; mi++)
                LDSM_X4(ah[mi], s_ah + a_row + mi * (16 * ROW_B) + kb + a_col);
#pragma unroll
            for (int h = 0; h < 2; h++)
                LDSM_X4(bq[h], s_bh + b_row + h * (16 * ROW_B) + kb + b_col);
            // ---- pass 1: Ah * Bh
#pragma unroll
            for (int mi = 0; mi < 4; mi++)
#pragma unroll
                for (int ni = 0; ni < 4; ni++)
                    MMA16816(acc[mi][ni], ah[mi],
                             bq[ni >> 1][(ni & 1) * 2], bq[ni >> 1][(ni & 1) * 2 + 1]);
            // ---- pass 2: Al * Bh
#pragma unroll
            for (int mi = 0; mi < 4; mi++)
                LDSM_X4(at[mi], s_al + a_row + mi * (16 * ROW_B) + kb + a_col);
#pragma unroll
            for (int mi = 0; mi < 4; mi++)
#pragma unroll
                for (int ni = 0; ni < 4; ni++)
                    MMA16816(acc[mi][ni], at[mi],
                             bq[ni >> 1][(ni & 1) * 2], bq[ni >> 1][(ni & 1) * 2 + 1]);
            // ---- pass 3: Ah * Bl
#pragma unroll
            for (int h = 0; h < 2; h++)
                LDSM_X4(bq[h], s_bl + b_row + h * (16 * ROW_B) + kb + b_col);
#pragma unroll
            for (int mi = 0; mi < 4; mi++)
#pragma unroll
                for (int ni = 0; ni < 4; ni++)
                    MMA16816(acc[mi][ni], ah[mi],
                             bq[ni >> 1][(ni & 1) * 2], bq[ni >> 1][(ni & 1) * 2 + 1]);
        }
        __syncthreads();   // stage reuse guard vs next iteration's prefetch
        stage++; if (stage >= NSTAGE) stage = 0;
    }

    // ---- epilogue: registers -> gmem (float2 stores)
    const int r_base = row0 + wm * 64 + (lane >> 2);
    const int c_base = col0 + wn * 32 + (lane & 3) * 2;
#pragma unroll
    for (int mi = 0; mi < 4; mi++) {
#pragma unroll
        for (int ni = 0; ni < 4; ni++) {
            int r = r_base + mi * 16;
            int c = c_base + ni * 8;
            float2 v0 = make_float2(acc[mi][ni][0], acc[mi][ni][1]);
            float2 v1 = make_float2(acc[mi][ni][2], acc[mi][ni][3]);
            *reinterpret_cast<float2*>(out + (size_t)r * N_DIM + c) = v0;
            *reinterpret_cast<float2*>(out + (size_t)(r + 8) * N_DIM + c) = v1;
        }
    }
}

// ============================================================================
// Host side
// ============================================================================
extern "C" void kernel_launch(void* const* d_in, const int* in_sizes, int n_in,
                              void* d_out, int out_size) {
    const float* x = (const float*)d_in[0];
    const float* w = (const float*)d_in[1];
    // x: 2*2048*4096 = 33554432 elems, weight: 4096*4096 = 16777216
    if (n_in >= 2 && in_sizes[0] < in_sizes[1]) {
        const float* t = x; x = w; w = t;
    }

    split_x_kernel<<<8192, 256>>>(x, (M_DIM * K_DIM) / 4);
    quant_split_w_kernel<<<(N_DIM * (K_DIM / GROUP_SIZE)) / 8, 256>>>(w);

    static_assert(SMEM_B <= 227 * 1024, "smem");
    cudaFuncSetAttribute(bitlinear_gemm_kernel,
                         cudaFuncAttributeMaxDynamicSharedMemorySize, SMEM_B);
    dim3 grid(N_DIM / BN, M_DIM / BM);
    bitlinear_gemm_kernel<<<grid, NTHREADS, SMEM_B>>>((float*)d_out);
}

// round 3
// speedup vs baseline: 1.5679x; 1.5679x over previous
#include <cuda_runtime.h>
#include <cuda_bf16.h>
#include <cstdint>

// ============================================================================
// out[4096,4096] = x @ w_q^T ;  w_q = groupwise ternary(weight)
// Path: q exact in int8; x = S_row/127^2 * (127*d0 + d1), d0,d1 int8.
// GEMM via mma.sync.m16n8k32.s8 (sm_100-legal), per-group scale fold in regs.
// ============================================================================
#define M_DIM 4096
#define N_DIM 4096
#define K_DIM 4096
#define GROUP_SIZE 128
#define NGROUPS (K_DIM / GROUP_SIZE)   // 32

#define BM 128
#define BN 128
#define BK 64                          // int8 elems (= bytes) per k-tile
#define KTILES (K_DIM / BK)            // 64
#define NSTAGE 3
#define NTHREADS 256

// smem rows: 64 data bytes + 16 pad = 80 B (stride 20 banks -> ldmatrix
// 8-row groups hit all 32 banks exactly once; conflict-free)
#define ROW_B 80
#define MAT_B (BM * ROW_B)             // 10240 B per 128x64 int8 tile
#define STAGE_B (3 * MAT_B)            // d0, d1, q planes
#define SC_B (BN * NGROUPS * 4)        // 16384 B scale tile
#define SMEM_B (SC_B + NSTAGE * STAGE_B)  // 108544

// ============================================================================
// Device-global scratch (allocation-free rule)
// ============================================================================
__device__ __align__(1024) int8_t g_d0[(size_t)M_DIM * K_DIM];
__device__ __align__(1024) int8_t g_d1[(size_t)M_DIM * K_DIM];
__device__ __align__(1024) int8_t g_q [(size_t)N_DIM * K_DIM];
__device__ __align__(256)  float  g_srow[M_DIM];
__device__ __align__(256)  float  g_wscale[N_DIM * NGROUPS];

// ============================================================================
// PTX helpers
// ============================================================================
__device__ __forceinline__ uint32_t smem_u32(const void* p) {
    uint32_t a;
    asm("{ .reg .u64 t; cvta.to.shared.u64 t, %1; cvt.u32.u64 %0, t; }"
        : "=r"(a) : "l"(p));
    return a;
}

#define CP_ASYNC_16(saddr, gaddr) \
    asm volatile("cp.async.cg.shared.global [%0], [%1], 16;" \
        :: "r"(saddr), "l"(gaddr))
#define CP_ASYNC_COMMIT() asm volatile("cp.async.commit_group;" ::: "memory")
#define CP_ASYNC_WAIT1()  asm volatile("cp.async.wait_group 1;" ::: "memory")

#define LDSM_X4(r, addr) \
    asm volatile("ldmatrix.sync.aligned.m8n8.x4.shared.b16 {%0,%1,%2,%3}, [%4];" \
        : "=r"((r)[0]), "=r"((r)[1]), "=r"((r)[2]), "=r"((r)[3]) : "r"(addr))

// s32 += s8 x s8 (m16n8k32), accumulate in place
#define IMMA16832(d, a, b0, b1) \
    asm volatile("mma.sync.aligned.m16n8k32.row.col.s32.s8.s8.s32 " \
        "{%0,%1,%2,%3}, {%4,%5,%6,%7}, {%8,%9}, {%0,%1,%2,%3};" \
        : "+r"((d)[0]), "+r"((d)[1]), "+r"((d)[2]), "+r"((d)[3]) \
        : "r"((a)[0]), "r"((a)[1]), "r"((a)[2]), "r"((a)[3]), "r"(b0), "r"(b1))

// s32 = s8 x s8 + 0  (group-start: implicit accumulator zeroing)
#define IMMA16832_ZC(d, a, b0, b1, z) \
    asm volatile("mma.sync.aligned.m16n8k32.row.col.s32.s8.s8.s32 " \
        "{%0,%1,%2,%3}, {%4,%5,%6,%7}, {%8,%9}, {%10,%10,%10,%10};" \
        : "=r"((d)[0]), "=r"((d)[1]), "=r"((d)[2]), "=r"((d)[3]) \
        : "r"((a)[0]), "r"((a)[1]), "r"((a)[2]), "r"((a)[3]), "r"(b0), "r"(b1), \
          "r"(z))

// ============================================================================
// Preprocess 1: per-row max + 2-digit base-127 split of x. One block per row.
// ============================================================================
__global__ void __launch_bounds__(256) digitize_x_kernel(const float* __restrict__ x) {
    __shared__ float red[256];
    const int m = blockIdx.x;
    const int tid = threadIdx.x;
    const float* xr = x + (size_t)m * K_DIM;

    float4 v[4];
    float mx = 0.0f;
#pragma unroll
    for (int j = 0; j < 4; j++) {
        v[j] = reinterpret_cast<const float4*>(xr)[tid + j * 256];
        mx = fmaxf(mx, fmaxf(fmaxf(fabsf(v[j].x), fabsf(v[j].y)),
                             fmaxf(fabsf(v[j].z), fabsf(v[j].w))));
    }
    red[tid] = mx;
    __syncthreads();
#pragma unroll
    for (int o = 128; o; o >>= 1) {
        if (tid < o) red[tid] = fmaxf(red[tid], red[tid + o]);
        __syncthreads();
    }
    const float S = fmaxf(red[0], 1e-30f);
    if (tid == 0) g_srow[m] = S;
    const float k = 127.0f / S;

#pragma unroll
    for (int j = 0; j < 4; j++) {
        float vals[4] = {v[j].x, v[j].y, v[j].z, v[j].w};
        char c0[4], c1[4];
#pragma unroll
        for (int e = 0; e < 4; e++) {
            float xs = vals[e] * k;          // in [-127, 127]
            float d0 = rintf(xs);
            float d1 = rintf((xs - d0) * 127.0f);   // in [-64, 64]
            c0[e] = (char)(int)d0;
            c1[e] = (char)(int)d1;
        }
        size_t base = (size_t)m * K_DIM + (tid + j * 256) * 4;
        *reinterpret_cast<char4*>(g_d0 + base) = make_char4(c0[0], c0[1], c0[2], c0[3]);
        *reinterpret_cast<char4*>(g_d1 + base) = make_char4(c1[0], c1[1], c1[2], c1[3]);
    }
}

// ============================================================================
// Preprocess 2: ternary-quantize weight groupwise -> q int8 + scale. Warp/group.
// ============================================================================
__global__ void quant_w_kernel(const float* __restrict__ w) {
    int warp = blockIdx.x * (blockDim.x >> 5) + (threadIdx.x >> 5);  // = n*32+g
    int lane = threadIdx.x & 31;
    const float4 v = reinterpret_cast<const float4*>(w + (size_t)warp * GROUP_SIZE)[lane];
    float s = fabsf(v.x) + fabsf(v.y) + fabsf(v.z) + fabsf(v.w);
#pragma unroll
    for (int o = 16; o; o >>= 1) s += __shfl_xor_sync(0xffffffffu, s, o);
    float scale = fmaxf(s * (1.0f / GROUP_SIZE), 1e-8f);
    if (lane == 0) g_wscale[warp] = scale;

    float vals[4] = {v.x, v.y, v.z, v.w};
    char q[4];
#pragma unroll
    for (int j = 0; j < 4; j++) {
        float wn = vals[j] / scale;
        q[j] = (wn > 0.5f) ? 1 : ((wn < -0.5f) ? -1 : 0);
    }
    *reinterpret_cast<char4*>(g_q + (size_t)warp * GROUP_SIZE + lane * 4) =
        make_char4(q[0], q[1], q[2], q[3]);
}

// ============================================================================
// GEMM: int8 IMMA, 2 digit planes, per-group fold of scale into fp32 acc.
// 128x128 CTA, 8 warps @ 64x32, BK=64, 3-stage cp.async pipeline.
// ============================================================================
__device__ __forceinline__ void prefetch_stage(uint32_t tbase, int stage, int kt,
                                               int row0, int col0, int tid) {
    uint32_t st = tbase + stage * STAGE_B;
    const int8_t* gsrc[3] = { g_d0, g_d1, g_q };
    int base_row[3] = { row0, row0, col0 };
#pragma unroll
    for (int p = 0; p < 3; p++) {
#pragma unroll
        for (int i = 0; i < 2; i++) {
            int chunk = tid + i * NTHREADS;   // 0..511
            int row = chunk >> 2;             // 0..127
            int c16 = chunk & 3;              // 16B chunk in 64B row
            const int8_t* g = gsrc[p] +
                (size_t)(base_row[p] + row) * K_DIM + kt * BK + c16 * 16;
            CP_ASYNC_16(st + p * MAT_B + row * ROW_B + c16 * 16, g);
        }
    }
}

__global__ void __launch_bounds__(NTHREADS, 1) bitlinear_imma_kernel(
    float* __restrict__ out)
{
    extern __shared__ __align__(128) unsigned char smem_raw[];
    const uint32_t sbase = smem_u32(smem_raw);
    const uint32_t sc_s  = sbase;              // [128 n][32 g] f32
    const uint32_t tbase = sbase + SC_B;       // pipeline stages
    const int tid = threadIdx.x;
    const int lane = tid & 31;
    const int wid = tid >> 5;
    const int wm = wid & 1;
    const int wn = wid >> 1;
    const int row0 = blockIdx.y * BM;
    const int col0 = blockIdx.x * BN;

    // cooperative load of this CTA's scale tile (contiguous in g_wscale)
    {
        const float* src = g_wscale + (size_t)col0 * NGROUPS;
        float* dst = reinterpret_cast<float*>(smem_raw);
#pragma unroll
        for (int j = 0; j < 4; j++) {
            reinterpret_cast<float4*>(dst)[tid + j * 256] =
                reinterpret_cast<const float4*>(src)[tid + j * 256];
        }
    }

    const uint32_t a_row = (wm * 64 + (lane & 15)) * ROW_B;
    const uint32_t a_col = (lane & 16) ? 16u : 0u;
    const uint32_t b_row = (wn * 32 + (lane & 7) + ((lane & 16) >> 1)) * ROW_B;
    const uint32_t b_col = (lane & 8) ? 16u : 0u;

    int   ac0[4][4][4], ac1[4][4][4];
    float accf[4][4][4];
    const int z0 = 0;
#pragma unroll
    for (int i = 0; i < 4; i++)
#pragma unroll
        for (int j = 0; j < 4; j++)
#pragma unroll
            for (int e = 0; e < 4; e++) accf[i][j][e] = 0.0f;

    prefetch_stage(tbase, 0, 0, row0, col0, tid);
    CP_ASYNC_COMMIT();
    prefetch_stage(tbase, 1, 1, row0, col0, tid);
    CP_ASYNC_COMMIT();

    int stage = 0;
    for (int kt = 0; kt < KTILES; kt++) {
        CP_ASYNC_WAIT1();
        __syncthreads();

        if (kt + 2 < KTILES) {
            int ns = stage + 2; if (ns >= NSTAGE) ns -= NSTAGE;
            prefetch_stage(tbase, ns, kt + 2, row0, col0, tid);
        }
        CP_ASYNC_COMMIT();

        const uint32_t st  = tbase + stage * STAGE_B;
        const uint32_t s_0 = st;                 // d0
        const uint32_t s_1 = st + MAT_B;         // d1
        const uint32_t s_q = st + 2 * MAT_B;     // q

        const bool gstart = ((kt & 1) == 0);     // group = 2 k-tiles
#pragma unroll
        for (int ks = 0; ks < 2; ks++) {         // two k32 steps
            const uint32_t kb = ks * 32;
            const bool zc = gstart && (ks == 0);

            uint32_t af[4][4], bq[2][4];
#pragma unroll
            for (int h = 0; h < 2; h++)
                LDSM_X4(bq[h], s_q + b_row + h * (16 * ROW_B) + kb + b_col);

            // ---- digit-0 plane
#pragma unroll
            for (int mi = 0; mi < 4; mi++)
                LDSM_X4(af[mi], s_0 + a_row + mi * (16 * ROW_B) + kb + a_col);
#pragma unroll
            for (int mi = 0; mi < 4; mi++)
#pragma unroll
                for (int ni = 0; ni < 4; ni++) {
                    if (zc) IMMA16832_ZC(ac0[mi][ni], af[mi],
                            bq[ni >> 1][(ni & 1) * 2], bq[ni >> 1][(ni & 1) * 2 + 1], z0);
                    else    IMMA16832(ac0[mi][ni], af[mi],
                            bq[ni >> 1][(ni & 1) * 2], bq[ni >> 1][(ni & 1) * 2 + 1]);
                }
            // ---- digit-1 plane
#pragma unroll
            for (int mi = 0; mi < 4; mi++)
                LDSM_X4(af[mi], s_1 + a_row + mi * (16 * ROW_B) + kb + a_col);
#pragma unroll
            for (int mi = 0; mi < 4; mi++)
#pragma unroll
                for (int ni = 0; ni < 4; ni++) {
                    if (zc) IMMA16832_ZC(ac1[mi][ni], af[mi],
                            bq[ni >> 1][(ni & 1) * 2], bq[ni >> 1][(ni & 1) * 2 + 1], z0);
                    else    IMMA16832(ac1[mi][ni], af[mi],
                            bq[ni >> 1][(ni & 1) * 2], bq[ni >> 1][(ni & 1) * 2 + 1]);
                }
        }

        // ---- group boundary: fold scale[n,g]*(127*A0 + A1) into fp32 acc
        if ((kt & 1) == 1) {
            const int g = kt >> 1;
            float sc[4][2];
#pragma unroll
            for (int ni = 0; ni < 4; ni++)
#pragma unroll
                for (int b = 0; b < 2; b++) {
                    int n_loc = wn * 32 + (lane & 3) * 2 + ni * 8 + b;
                    asm volatile("ld.shared.f32 %0, [%1];"
                        : "=f"(sc[ni][b])
                        : "r"(sc_s + (uint32_t)(n_loc * NGROUPS + g) * 4));
                }
#pragma unroll
            for (int mi = 0; mi < 4; mi++)
#pragma unroll
                for (int ni = 0; ni < 4; ni++)
#pragma unroll
                    for (int e = 0; e < 4; e++) {
                        int t = ac0[mi][ni][e] * 127 + ac1[mi][ni][e];
                        accf[mi][ni][e] = fmaf((float)t, sc[ni][e & 1],
                                               accf[mi][ni][e]);
                    }
        }

        __syncthreads();
        stage++; if (stage >= NSTAGE) stage = 0;
    }

    // ---- epilogue: out = accf * S_row / 127^2
    const int r_base = row0 + wm * 64 + (lane >> 2);
    const int c_base = col0 + wn * 32 + (lane & 3) * 2;
    float sm[4][2];
#pragma unroll
    for (int mi = 0; mi < 4; mi++)
#pragma unroll
        for (int h = 0; h < 2; h++)
            sm[mi][h] = g_srow[r_base + mi * 16 + h * 8] * (1.0f / 16129.0f);

#pragma unroll
    for (int mi = 0; mi < 4; mi++) {
#pragma unroll
        for (int ni = 0; ni < 4; ni++) {
            int r = r_base + mi * 16;
            int c = c_base + ni * 8;
            float2 v0 = make_float2(accf[mi][ni][0] * sm[mi][0],
                                    accf[mi][ni][1] * sm[mi][0]);
            float2 v1 = make_float2(accf[mi][ni][2] * sm[mi][1],
                                    accf[mi][ni][3] * sm[mi][1]);
            *reinterpret_cast<float2*>(out + (size_t)r * N_DIM + c) = v0;
            *reinterpret_cast<float2*>(out + (size_t)(r + 8) * N_DIM + c) = v1;
        }
    }
}

// ============================================================================
// Host side
// ============================================================================
extern "C" void kernel_launch(void* const* d_in, const int* in_sizes, int n_in,
                              void* d_out, int out_size) {
    const float* x = (const float*)d_in[0];
    const float* w = (const float*)d_in[1];
    if (n_in >= 2 && in_sizes[0] < in_sizes[1]) {  // x is the bigger input
        const float* t = x; x = w; w = t;
    }

    digitize_x_kernel<<<M_DIM, 256>>>(x);
    quant_w_kernel<<<(N_DIM * NGROUPS) / 8, 256>>>(w);

    static_assert(SMEM_B <= 227 * 1024, "smem");
    cudaFuncSetAttribute(bitlinear_imma_kernel,
                         cudaFuncAttributeMaxDynamicSharedMemorySize, SMEM_B);
    dim3 grid(N_DIM / BN, M_DIM / BM);
    bitlinear_imma_kernel<<<grid, NTHREADS, SMEM_B>>>((float*)d_out);
}